// round 5
// baseline (speedup 1.0000x reference)
#include <cuda_runtime.h>
#include <cstdint>
#include <math.h>

#define DIMX   1536
#define QKVD   4608
#define NHEADS 24
#define HDIM   64
#define BB     2
#define NXX    2048
#define NCC    256
#define NTOTAL 2304
#define ATT_SCALE 0.125f
#define SSTR   68
#define GSTR   20

// Scratch [B,H,N,D]
__device__ float g_q[(size_t)BB*NHEADS*NTOTAL*HDIM];
__device__ float g_k[(size_t)BB*NHEADS*NTOTAL*HDIM];
__device__ float g_v[(size_t)BB*NHEADS*NTOTAL*HDIM];
__device__ float g_o[(size_t)BB*NHEADS*NTOTAL*HDIM];

__device__ __forceinline__ uint32_t f2tf(float x) {
    uint32_t u;
    asm("cvt.rna.tf32.f32 %0, %1;" : "=r"(u) : "f"(x));
    return u;
}
__device__ __forceinline__ uint32_t u2tf(uint32_t ubits) {
    uint32_t u;
    asm("cvt.rna.tf32.f32 %0, %1;" : "=r"(u) : "f"(__uint_as_float(ubits)));
    return u;
}

__device__ __forceinline__ void mma_tf32(float* d, const uint32_t* a, uint32_t b0, uint32_t b1) {
    asm volatile(
        "mma.sync.aligned.m16n8k8.row.col.f32.tf32.tf32.f32 "
        "{%0,%1,%2,%3}, {%4,%5,%6,%7}, {%8,%9}, {%0,%1,%2,%3};"
        : "+f"(d[0]), "+f"(d[1]), "+f"(d[2]), "+f"(d[3])
        : "r"(a[0]), "r"(a[1]), "r"(a[2]), "r"(a[3]), "r"(b0), "r"(b1));
}

__device__ __forceinline__ uint32_t s2u(const void* p) {
    return (uint32_t)__cvta_generic_to_shared(p);
}
__device__ __forceinline__ void cp16(uint32_t dst, const void* src) {
    asm volatile("cp.async.cg.shared.global [%0], [%1], 16;" :: "r"(dst), "l"(src));
}
#define CP_COMMIT() asm volatile("cp.async.commit_group;" ::: "memory")
#define CP_WAIT0()  asm volatile("cp.async.wait_group 0;" ::: "memory")
#define CP_WAIT1()  asm volatile("cp.async.wait_group 1;" ::: "memory")

// ===========================================================================
// GEMM compute core: 128x128 block tile, 8 warps (4x2), warp tile 32x64
// ===========================================================================
__device__ __forceinline__ void gemm_tile_compute(
    const uint32_t* __restrict__ As, const uint32_t* __restrict__ Bs,
    int mbase, int nbase, int qg, int qt, float acc[2][8][4])
{
#pragma unroll
    for (int kf = 0; kf < 2; kf++) {
        int kc = kf * 8;
        uint32_t a[2][4], b[8][2];
#pragma unroll
        for (int mf = 0; mf < 2; mf++) {
            int r = mbase + mf * 16;
            a[mf][0] = As[(r + qg) * GSTR + kc + qt];
            a[mf][1] = As[(r + qg + 8) * GSTR + kc + qt];
            a[mf][2] = As[(r + qg) * GSTR + kc + qt + 4];
            a[mf][3] = As[(r + qg + 8) * GSTR + kc + qt + 4];
        }
#pragma unroll
        for (int nf = 0; nf < 8; nf++) {
            int c = nbase + nf * 8;
            b[nf][0] = Bs[(c + qg) * GSTR + kc + qt];
            b[nf][1] = Bs[(c + qg) * GSTR + kc + qt + 4];
        }
#pragma unroll
        for (int mf = 0; mf < 2; mf++)
#pragma unroll
            for (int nf = 0; nf < 8; nf++)
                mma_tf32(acc[mf][nf], a[mf], b[nf][0], b[nf][1]);
    }
}

// ---------------------------------------------------------------------------
// QKV GEMM, double-buffered smem with register-staged prefetch
// ---------------------------------------------------------------------------
__global__ __launch_bounds__(256) void qkv_mma_kernel(
    const float* __restrict__ A, const float* __restrict__ W,
    const float* __restrict__ bias, int Nt, int n_off)
{
    __shared__ uint32_t As[2][128 * GSTR];
    __shared__ uint32_t Bs[2][128 * GSTR];
    const int tid = threadIdx.x;
    const int w = tid >> 5, lane = tid & 31;
    const int qg = lane >> 2, qt = lane & 3;
    const int mbase = (w & 3) * 32, nbase = (w >> 2) * 64;
    const int rowBase = blockIdx.y * 128;
    const int colBase = blockIdx.x * 128;

    // loader slot (two slots per thread)
    int lr[2], lk[2];
#pragma unroll
    for (int i = 0; i < 2; i++) {
        int lin = tid + i * 256;
        lr[i] = lin >> 2; lk[i] = (lin & 3) << 2;
    }

    float acc[2][8][4];
#pragma unroll
    for (int mf = 0; mf < 2; mf++)
#pragma unroll
        for (int nf = 0; nf < 8; nf++)
#pragma unroll
            for (int e = 0; e < 4; e++) acc[mf][nf][e] = 0.f;

    float4 pa[2], pw[2];
    // prologue: k0 = 0
#pragma unroll
    for (int i = 0; i < 2; i++) {
        pa[i] = *(const float4*)(A + (size_t)(rowBase + lr[i]) * DIMX + lk[i]);
        pw[i] = *(const float4*)(W + (size_t)(colBase + lr[i]) * DIMX + lk[i]);
    }
#pragma unroll
    for (int i = 0; i < 2; i++) {
        uint32_t* da = &As[0][lr[i] * GSTR + lk[i]];
        da[0] = f2tf(pa[i].x); da[1] = f2tf(pa[i].y); da[2] = f2tf(pa[i].z); da[3] = f2tf(pa[i].w);
        uint32_t* db = &Bs[0][lr[i] * GSTR + lk[i]];
        db[0] = f2tf(pw[i].x); db[1] = f2tf(pw[i].y); db[2] = f2tf(pw[i].z); db[3] = f2tf(pw[i].w);
    }
    __syncthreads();

    int buf = 0;
    for (int k0 = 0; k0 < DIMX; k0 += 16) {
        const int kn = k0 + 16;
        const bool has = kn < DIMX;
        if (has) {
#pragma unroll
            for (int i = 0; i < 2; i++) {
                pa[i] = *(const float4*)(A + (size_t)(rowBase + lr[i]) * DIMX + kn + lk[i]);
                pw[i] = *(const float4*)(W + (size_t)(colBase + lr[i]) * DIMX + kn + lk[i]);
            }
        }
        gemm_tile_compute(As[buf], Bs[buf], mbase, nbase, qg, qt, acc);
        if (has) {
#pragma unroll
            for (int i = 0; i < 2; i++) {
                uint32_t* da = &As[buf ^ 1][lr[i] * GSTR + lk[i]];
                da[0] = f2tf(pa[i].x); da[1] = f2tf(pa[i].y); da[2] = f2tf(pa[i].z); da[3] = f2tf(pa[i].w);
                uint32_t* db = &Bs[buf ^ 1][lr[i] * GSTR + lk[i]];
                db[0] = f2tf(pw[i].x); db[1] = f2tf(pw[i].y); db[2] = f2tf(pw[i].z); db[3] = f2tf(pw[i].w);
            }
            __syncthreads();
        }
        buf ^= 1;
    }

#pragma unroll
    for (int mf = 0; mf < 2; mf++) {
#pragma unroll
        for (int er = 0; er < 2; er++) {
            int r = rowBase + mbase + mf * 16 + qg + er * 8;
            int bi = r / Nt;
            int n = r - bi * Nt;
#pragma unroll
            for (int nf = 0; nf < 8; nf++) {
                int cidx = colBase + nbase + nf * 8 + 2 * qt;
                float v0 = acc[mf][nf][er * 2 + 0] + bias[cidx];
                float v1 = acc[mf][nf][er * 2 + 1] + bias[cidx + 1];
                int three = cidx / DIMX;
                int rem = cidx - three * DIMX;
                int h = rem >> 6, d = rem & 63;
                float* dst = (three == 0) ? g_q : (three == 1) ? g_k : g_v;
                *(float2*)(dst + (((size_t)bi * NHEADS + h) * NTOTAL + (n_off + n)) * HDIM + d)
                    = make_float2(v0, v1);
            }
        }
    }
}

// ---------------------------------------------------------------------------
// Flash attention, cp.async double-buffered K/V (raw fp32 in smem,
// tf32 cvt at fragment load). Dynamic smem: Qs + 2*Ks + 2*Vs.
// ---------------------------------------------------------------------------
#define ATT_TILE_U32 (64 * SSTR)
#define ATT_SMEM_BYTES (5 * ATT_TILE_U32 * 4)

__global__ __launch_bounds__(128) void attn_mma_kernel()
{
    extern __shared__ uint32_t sm[];
    uint32_t* Qs = sm;                      // 64*SSTR (tf32) — becomes Ps
    uint32_t* Kb[2] = { sm + ATT_TILE_U32, sm + 2 * ATT_TILE_U32 };
    uint32_t* Vb[2] = { sm + 3 * ATT_TILE_U32, sm + 4 * ATT_TILE_U32 };

    const int tid = threadIdx.x;
    const int w = tid >> 5, lane = tid & 31;
    const int qg = lane >> 2, qt = lane & 3;
    const int h = blockIdx.y, bi = blockIdx.z;
    const size_t headbase = ((size_t)bi * NHEADS + h) * NTOTAL;
    const int qbase = blockIdx.x * 64;
    const int mrow = w * 16;

    // issue one K/V tile via cp.async
    auto issue_tile = [&](int jt, int b) {
        uint32_t kdst = s2u(Kb[b]);
        uint32_t vdst = s2u(Vb[b]);
#pragma unroll
        for (int i = 0; i < 8; i++) {
            int lin = tid + i * 128;
            int r = lin >> 4, c4 = (lin & 15) << 2;
            uint32_t off = (uint32_t)(r * SSTR + c4) * 4u;
            cp16(kdst + off, g_k + (headbase + jt + r) * HDIM + c4);
            cp16(vdst + off, g_v + (headbase + jt + r) * HDIM + c4);
        }
        CP_COMMIT();
    };

    issue_tile(0, 0);

    // stage Q (tf32) while K/V tile 0 is in flight
#pragma unroll
    for (int i = 0; i < 8; i++) {
        int lin = tid + i * 128;
        int r = lin >> 4, c4 = (lin & 15) << 2;
        float4 t = *(const float4*)(g_q + (headbase + qbase + r) * HDIM + c4);
        uint32_t* d = &Qs[r * SSTR + c4];
        d[0] = f2tf(t.x); d[1] = f2tf(t.y); d[2] = f2tf(t.z); d[3] = f2tf(t.w);
    }
    __syncthreads();

    uint32_t qf[8][4];
#pragma unroll
    for (int kf = 0; kf < 8; kf++) {
        int kc = kf * 8;
        qf[kf][0] = Qs[(mrow + qg) * SSTR + kc + qt];
        qf[kf][1] = Qs[(mrow + qg + 8) * SSTR + kc + qt];
        qf[kf][2] = Qs[(mrow + qg) * SSTR + kc + qt + 4];
        qf[kf][3] = Qs[(mrow + qg + 8) * SSTR + kc + qt + 4];
    }
    __syncthreads();
    uint32_t* Ps = Qs;

    float of[8][4];
#pragma unroll
    for (int nf = 0; nf < 8; nf++)
#pragma unroll
        for (int e = 0; e < 4; e++) of[nf][e] = 0.f;
    float m0 = -1e30f, m1 = -1e30f, l0 = 0.f, l1 = 0.f;

    int buf = 0;
    for (int jt = 0; jt < NTOTAL; jt += 64) {
        const bool has = (jt + 64) < NTOTAL;
        if (has) issue_tile(jt + 64, buf ^ 1);
        if (has) { CP_WAIT1(); } else { CP_WAIT0(); }
        __syncthreads();

        const uint32_t* Kc = Kb[buf];
        const uint32_t* Vc = Vb[buf];

        // S = Q K^T
        float sf[8][4];
#pragma unroll
        for (int nf = 0; nf < 8; nf++)
#pragma unroll
            for (int e = 0; e < 4; e++) sf[nf][e] = 0.f;
#pragma unroll
        for (int kf = 0; kf < 8; kf++) {
            int kc = kf * 8;
#pragma unroll
            for (int nf = 0; nf < 8; nf++) {
                uint32_t b0 = u2tf(Kc[(nf * 8 + qg) * SSTR + kc + qt]);
                uint32_t b1 = u2tf(Kc[(nf * 8 + qg) * SSTR + kc + qt + 4]);
                mma_tf32(sf[nf], qf[kf], b0, b1);
            }
        }

        // online softmax (rows warp-private; quad reduce via shfl)
        float mx0 = -1e30f, mx1 = -1e30f;
#pragma unroll
        for (int nf = 0; nf < 8; nf++) {
            sf[nf][0] *= ATT_SCALE; sf[nf][1] *= ATT_SCALE;
            sf[nf][2] *= ATT_SCALE; sf[nf][3] *= ATT_SCALE;
            mx0 = fmaxf(mx0, fmaxf(sf[nf][0], sf[nf][1]));
            mx1 = fmaxf(mx1, fmaxf(sf[nf][2], sf[nf][3]));
        }
        mx0 = fmaxf(mx0, __shfl_xor_sync(0xffffffffu, mx0, 1));
        mx0 = fmaxf(mx0, __shfl_xor_sync(0xffffffffu, mx0, 2));
        mx1 = fmaxf(mx1, __shfl_xor_sync(0xffffffffu, mx1, 1));
        mx1 = fmaxf(mx1, __shfl_xor_sync(0xffffffffu, mx1, 2));

        float nm0 = fmaxf(m0, mx0), nm1 = fmaxf(m1, mx1);
        float corr0 = __expf(m0 - nm0), corr1 = __expf(m1 - nm1);
        float s0 = 0.f, s1 = 0.f;
#pragma unroll
        for (int nf = 0; nf < 8; nf++) {
            float p00 = __expf(sf[nf][0] - nm0);
            float p01 = __expf(sf[nf][1] - nm0);
            float p10 = __expf(sf[nf][2] - nm1);
            float p11 = __expf(sf[nf][3] - nm1);
            s0 += p00 + p01; s1 += p10 + p11;
            int col = nf * 8 + 2 * qt;
            Ps[(mrow + qg) * SSTR + col]     = f2tf(p00);
            Ps[(mrow + qg) * SSTR + col + 1] = f2tf(p01);
            Ps[(mrow + qg + 8) * SSTR + col]     = f2tf(p10);
            Ps[(mrow + qg + 8) * SSTR + col + 1] = f2tf(p11);
            of[nf][0] *= corr0; of[nf][1] *= corr0;
            of[nf][2] *= corr1; of[nf][3] *= corr1;
        }
        s0 += __shfl_xor_sync(0xffffffffu, s0, 1);
        s0 += __shfl_xor_sync(0xffffffffu, s0, 2);
        s1 += __shfl_xor_sync(0xffffffffu, s1, 1);
        s1 += __shfl_xor_sync(0xffffffffu, s1, 2);
        l0 = l0 * corr0 + s0; l1 = l1 * corr1 + s1;
        m0 = nm0; m1 = nm1;
        __syncwarp();

        // O += P @ V
#pragma unroll
        for (int kf = 0; kf < 8; kf++) {
            int jc = kf * 8;
            uint32_t a[4];
            a[0] = Ps[(mrow + qg) * SSTR + jc + qt];
            a[1] = Ps[(mrow + qg + 8) * SSTR + jc + qt];
            a[2] = Ps[(mrow + qg) * SSTR + jc + qt + 4];
            a[3] = Ps[(mrow + qg + 8) * SSTR + jc + qt + 4];
#pragma unroll
            for (int nf = 0; nf < 8; nf++) {
                uint32_t b0 = u2tf(Vc[(jc + qt) * SSTR + nf * 8 + qg]);
                uint32_t b1 = u2tf(Vc[(jc + qt + 4) * SSTR + nf * 8 + qg]);
                mma_tf32(of[nf], a, b0, b1);
            }
        }
        __syncthreads();
        buf ^= 1;
    }

    const float inv0 = 1.f / l0, inv1 = 1.f / l1;
    const int row0 = qbase + mrow + qg, row1 = row0 + 8;
#pragma unroll
    for (int nf = 0; nf < 8; nf++) {
        int col = nf * 8 + 2 * qt;
        *(float2*)(g_o + (headbase + row0) * HDIM + col)
            = make_float2(of[nf][0] * inv0, of[nf][1] * inv0);
        *(float2*)(g_o + (headbase + row1) * HDIM + col)
            = make_float2(of[nf][2] * inv1, of[nf][3] * inv1);
    }
}

// ---------------------------------------------------------------------------
// Projection GEMM, double-buffered, A gathered from g_o [B,H,N,D]
// ---------------------------------------------------------------------------
__global__ __launch_bounds__(256) void proj_mma_kernel(
    const float* __restrict__ W, const float* __restrict__ bias,
    float* __restrict__ out, int Nt, int n_off)
{
    __shared__ uint32_t As[2][128 * GSTR];
    __shared__ uint32_t Bs[2][128 * GSTR];
    const int tid = threadIdx.x;
    const int w = tid >> 5, lane = tid & 31;
    const int qg = lane >> 2, qt = lane & 3;
    const int mbase = (w & 3) * 32, nbase = (w >> 2) * 64;
    const int rowBase = blockIdx.y * 128;
    const int colBase = blockIdx.x * 128;

    int lr[2], lk[2];
    size_t abase[2];
#pragma unroll
    for (int i = 0; i < 2; i++) {
        int lin = tid + i * 256;
        lr[i] = lin >> 2; lk[i] = (lin & 3) << 2;
        int row = rowBase + lr[i];
        int bi = row / Nt;
        int n = row - bi * Nt;
        abase[i] = ((size_t)bi * NHEADS * NTOTAL + (n_off + n)) * HDIM;  // + h*NTOTAL*HDIM + d
    }

    float acc[2][8][4];
#pragma unroll
    for (int mf = 0; mf < 2; mf++)
#pragma unroll
        for (int nf = 0; nf < 8; nf++)
#pragma unroll
            for (int e = 0; e < 4; e++) acc[mf][nf][e] = 0.f;

    auto fetch = [&](int k0, float4* pa, float4* pw) {
#pragma unroll
        for (int i = 0; i < 2; i++) {
            int k = k0 + lk[i];
            int hh = k >> 6, dd = k & 63;
            pa[i] = *(const float4*)(g_o + abase[i] + (size_t)hh * NTOTAL * HDIM + dd);
            pw[i] = *(const float4*)(W + (size_t)(colBase + lr[i]) * DIMX + k0 + lk[i]);
        }
    };
    auto store = [&](int b, const float4* pa, const float4* pw) {
#pragma unroll
        for (int i = 0; i < 2; i++) {
            uint32_t* da = &As[b][lr[i] * GSTR + lk[i]];
            da[0] = f2tf(pa[i].x); da[1] = f2tf(pa[i].y); da[2] = f2tf(pa[i].z); da[3] = f2tf(pa[i].w);
            uint32_t* db = &Bs[b][lr[i] * GSTR + lk[i]];
            db[0] = f2tf(pw[i].x); db[1] = f2tf(pw[i].y); db[2] = f2tf(pw[i].z); db[3] = f2tf(pw[i].w);
        }
    };

    float4 pa[2], pw[2];
    fetch(0, pa, pw);
    store(0, pa, pw);
    __syncthreads();

    int buf = 0;
    for (int k0 = 0; k0 < DIMX; k0 += 16) {
        const int kn = k0 + 16;
        const bool has = kn < DIMX;
        if (has) fetch(kn, pa, pw);
        gemm_tile_compute(As[buf], Bs[buf], mbase, nbase, qg, qt, acc);
        if (has) {
            store(buf ^ 1, pa, pw);
            __syncthreads();
        }
        buf ^= 1;
    }

#pragma unroll
    for (int mf = 0; mf < 2; mf++) {
#pragma unroll
        for (int er = 0; er < 2; er++) {
            int r = rowBase + mbase + mf * 16 + qg + er * 8;
#pragma unroll
            for (int nf = 0; nf < 8; nf++) {
                int cidx = colBase + nbase + nf * 8 + 2 * qt;
                float v0 = acc[mf][nf][er * 2 + 0] + bias[cidx];
                float v1 = acc[mf][nf][er * 2 + 1] + bias[cidx + 1];
                *(float2*)(out + (size_t)r * DIMX + cidx) = make_float2(v0, v1);
            }
        }
    }
}

// ---------------------------------------------------------------------------
extern "C" void kernel_launch(void* const* d_in, const int* in_sizes, int n_in,
                              void* d_out, int out_size)
{
    const float* x       = (const float*)d_in[0];
    const float* c       = (const float*)d_in[1];
    const float* Wqkv_x  = (const float*)d_in[2];
    const float* bqkv_x  = (const float*)d_in[3];
    const float* Wqkv_c  = (const float*)d_in[4];
    const float* bqkv_c  = (const float*)d_in[5];
    const float* Wproj_x = (const float*)d_in[6];
    const float* bproj_x = (const float*)d_in[7];
    const float* Wproj_c = (const float*)d_in[8];
    const float* bproj_c = (const float*)d_in[9];
    float* out = (float*)d_out;

    cudaFuncSetAttribute(attn_mma_kernel,
                         cudaFuncAttributeMaxDynamicSharedMemorySize, ATT_SMEM_BYTES);

    qkv_mma_kernel<<<dim3(QKVD / 128, (BB * NXX) / 128), 256>>>(x, Wqkv_x, bqkv_x, NXX, 0);
    qkv_mma_kernel<<<dim3(QKVD / 128, (BB * NCC) / 128), 256>>>(c, Wqkv_c, bqkv_c, NCC, NXX);

    attn_mma_kernel<<<dim3(NTOTAL / 64, NHEADS, BB), 128, ATT_SMEM_BYTES>>>();

    proj_mma_kernel<<<dim3(DIMX / 128, (BB * NXX) / 128), 256>>>(
        Wproj_x, bproj_x, out, NXX, 0);
    proj_mma_kernel<<<dim3(DIMX / 128, (BB * NCC) / 128), 256>>>(
        Wproj_c, bproj_c, out + (size_t)BB * NXX * DIMX, NCC, NXX);
}